// round 1
// baseline (speedup 1.0000x reference)
#include <cuda_runtime.h>
#include <cuda_bf16.h>
#include <cstdint>

// ---------------- problem constants ----------------
#define BSZ        4
#define DIM        512
#define D_INNER    1024
#define HEADDIM    128
#define NHEADS     8
#define D_STATE    128
#define D_CONV     4
#define CONV_DIM   1280          // D_INNER + 2*D_STATE
#define D_IN_PROJ  2312          // 2*D_INNER + 2*D_STATE + NHEADS
#define LSEQ       4096          // 16*16*16
#define NBL        (BSZ * LSEQ)  // 16384 rows (b,l)

// ---------------- device scratch (static globals; no allocation) ----------------
__device__ float g_zx  [(size_t)NBL * D_IN_PROJ];   // in_proj output (z | xBC | dt_raw)
__device__ float g_conv[(size_t)NBL * CONV_DIM];    // conv+silu output (xs | B | C)
__device__ float g_dt  [NBL * NHEADS];
__device__ float g_dA  [NBL * NHEADS];
__device__ float g_y   [(size_t)NBL * D_INNER];     // scan output, then normed in-place

// =====================================================================
// GEMM1: zxbcdt[m][n] = sum_k x[b][k][l] * W[n][k],  m = b*4096 + l
// M=16384, N=2312, K=512.  128x128x8 tile, 256 threads, 8x8 microtile.
// =====================================================================
__global__ __launch_bounds__(256) void gemm1_kernel(const float* __restrict__ x,
                                                    const float* __restrict__ W) {
    __shared__ float As[8][128];    // [k][m]
    __shared__ float Bs[8][132];    // [k][n] (padded)
    const int tid = threadIdx.x;
    const int m0  = blockIdx.y * 128;
    const int n0  = blockIdx.x * 128;
    const int b   = m0 >> 12;
    const int l0  = m0 & 4095;
    const float* Ap = x + (size_t)b * DIM * LSEQ + l0;   // + k*4096 + m_local

    const int tx = tid & 15, ty = tid >> 4;
    const int ka = tid >> 5;            // 0..7
    const int ma = (tid & 31) * 4;      // 0..124
    const int nb = tid >> 1;            // 0..127
    const int kb = (tid & 1) * 4;       // 0 or 4

    const int nglob = n0 + nb;
    const bool nval = (nglob < D_IN_PROJ);

    float acc[8][8];
#pragma unroll
    for (int i = 0; i < 8; i++)
#pragma unroll
        for (int j = 0; j < 8; j++) acc[i][j] = 0.f;

    for (int k0 = 0; k0 < DIM; k0 += 8) {
        float4 av = *(const float4*)(Ap + (size_t)(k0 + ka) * LSEQ + ma);
        float4 bv = make_float4(0.f, 0.f, 0.f, 0.f);
        if (nval) bv = *(const float4*)(W + (size_t)nglob * DIM + k0 + kb);
        *(float4*)&As[ka][ma] = av;
        Bs[kb + 0][nb] = bv.x; Bs[kb + 1][nb] = bv.y;
        Bs[kb + 2][nb] = bv.z; Bs[kb + 3][nb] = bv.w;
        __syncthreads();
#pragma unroll
        for (int kk = 0; kk < 8; kk++) {
            float a[8], bb[8];
            *(float4*)&a[0]  = *(float4*)&As[kk][ty * 8];
            *(float4*)&a[4]  = *(float4*)&As[kk][ty * 8 + 4];
            *(float4*)&bb[0] = *(float4*)&Bs[kk][tx * 8];
            *(float4*)&bb[4] = *(float4*)&Bs[kk][tx * 8 + 4];
#pragma unroll
            for (int i = 0; i < 8; i++)
#pragma unroll
                for (int j = 0; j < 8; j++)
                    acc[i][j] = fmaf(a[i], bb[j], acc[i][j]);
        }
        __syncthreads();
    }

    const bool full = (n0 + 128 <= D_IN_PROJ);
#pragma unroll
    for (int i = 0; i < 8; i++) {
        const int m = m0 + ty * 8 + i;
        float* op = g_zx + (size_t)m * D_IN_PROJ + n0 + tx * 8;
        if (full) {
            *(float4*)op       = make_float4(acc[i][0], acc[i][1], acc[i][2], acc[i][3]);
            *(float4*)(op + 4) = make_float4(acc[i][4], acc[i][5], acc[i][6], acc[i][7]);
        } else {
#pragma unroll
            for (int j = 0; j < 8; j++)
                if (n0 + tx * 8 + j < D_IN_PROJ) op[j] = acc[i][j];
        }
    }
}

// =====================================================================
// prep: dt = softplus(dt_raw + dt_bias); dA = exp(dt * (-exp(A_log)))
// =====================================================================
__global__ __launch_bounds__(256) void prep_kernel(const float* __restrict__ dt_bias,
                                                   const float* __restrict__ A_log) {
    const int gid = blockIdx.x * 256 + threadIdx.x;   // < NBL*NHEADS = 131072
    const int bl = gid >> 3, h = gid & 7;
    float v = g_zx[(size_t)bl * D_IN_PROJ + (D_INNER + CONV_DIM) + h] + dt_bias[h];
    float dt = (v > 20.f) ? v : log1pf(expf(v));
    float A = -expf(A_log[h]);
    g_dt[gid] = dt;
    g_dA[gid] = expf(dt * A);
}

// =====================================================================
// conv: causal depthwise conv over l (width 4) + bias, then SiLU.
// g_conv[bl][c] over c in [0, 1280)
// =====================================================================
__global__ __launch_bounds__(256) void conv_kernel(const float* __restrict__ conv_w,
                                                   const float* __restrict__ conv_b) {
    const int gid = blockIdx.x * 256 + threadIdx.x;   // exactly NBL*CONV_DIM
    const int bl = gid / CONV_DIM;
    const int c  = gid - bl * CONV_DIM;
    const int l  = bl & 4095;
    const float w0 = conv_w[c * 4 + 0], w1 = conv_w[c * 4 + 1];
    const float w2 = conv_w[c * 4 + 2], w3 = conv_w[c * 4 + 3];
    const float* base = g_zx + (size_t)bl * D_IN_PROJ + D_INNER + c;
    float acc = conv_b[c];
    if (l >= 3) {
        acc += base[-3 * D_IN_PROJ] * w0;
        acc += base[-2 * D_IN_PROJ] * w1;
        acc += base[-1 * D_IN_PROJ] * w2;
        acc += base[0] * w3;
    } else {
        if (l >= 3) acc += base[-3 * D_IN_PROJ] * w0;
        if (l >= 2) acc += base[-2 * D_IN_PROJ] * w1;
        if (l >= 1) acc += base[-1 * D_IN_PROJ] * w2;
        acc += base[0] * w3;
    }
    g_conv[gid] = acc / (1.f + expf(-acc));
}

// =====================================================================
// scan: selective state-space scan.
// block = (b, h, p-tile of 32). 256 threads = 8 warps.
// warp w owns p rows {p0+4w .. p0+4w+3}; lane owns n = {4*lane .. 4*lane+3}.
// state: 4x4 floats in registers per thread. 8 timesteps staged in SMEM.
// =====================================================================
__global__ __launch_bounds__(256) void scan_kernel(const float* __restrict__ D_param) {
    __shared__ float Bs[8][128], Cs[8][128], Xs[8][32];
    __shared__ float dts[8], dAs[8];
    const int tid  = threadIdx.x;
    const int lane = tid & 31, w = tid >> 5;
    const int bid = blockIdx.x;
    const int b  = bid >> 5;
    const int h  = (bid >> 2) & 7;
    const int p0 = (bid & 3) * 32;
    const float Dh = D_param[h];
    const int blbase = b << 12;

    float s[4][4];
#pragma unroll
    for (int i = 0; i < 4; i++)
#pragma unroll
        for (int j = 0; j < 4; j++) s[i][j] = 0.f;

    for (int cchunk = 0; cchunk < LSEQ / 8; cchunk++) {
        const int t0 = cchunk * 8;
        __syncthreads();
        // stage B, C for 8 steps
        for (int j = tid; j < 8 * 128; j += 256) {
            const int tt = j >> 7, n = j & 127;
            const float* row = g_conv + (size_t)(blbase + t0 + tt) * CONV_DIM;
            Bs[tt][n] = row[D_INNER + n];
            Cs[tt][n] = row[D_INNER + D_STATE + n];
        }
        // stage x for this head's p-tile (8 steps x 32 p = 256)
        {
            const int tt = tid >> 5, pp = tid & 31;
            Xs[tt][pp] = g_conv[(size_t)(blbase + t0 + tt) * CONV_DIM + h * HEADDIM + p0 + pp];
        }
        if (tid < 8) {
            dts[tid] = g_dt[(blbase + t0 + tid) * NHEADS + h];
            dAs[tid] = g_dA[(blbase + t0 + tid) * NHEADS + h];
        }
        __syncthreads();
#pragma unroll
        for (int tt = 0; tt < 8; tt++) {
            const float dA = dAs[tt], dtv = dts[tt];
            const float4 Bv = *(const float4*)&Bs[tt][lane * 4];
            const float4 Cv = *(const float4*)&Cs[tt][lane * 4];
            float yv[4], xv[4];
#pragma unroll
            for (int i = 0; i < 4; i++) {
                const float xi = Xs[tt][w * 4 + i];
                xv[i] = xi;
                const float dtx = xi * dtv;
                s[i][0] = fmaf(dtx, Bv.x, s[i][0] * dA);
                s[i][1] = fmaf(dtx, Bv.y, s[i][1] * dA);
                s[i][2] = fmaf(dtx, Bv.z, s[i][2] * dA);
                s[i][3] = fmaf(dtx, Bv.w, s[i][3] * dA);
                float y = s[i][0] * Cv.x;
                y = fmaf(s[i][1], Cv.y, y);
                y = fmaf(s[i][2], Cv.z, y);
                y = fmaf(s[i][3], Cv.w, y);
                yv[i] = y;
            }
#pragma unroll
            for (int i = 0; i < 4; i++) {
#pragma unroll
                for (int off = 16; off > 0; off >>= 1)
                    yv[i] += __shfl_xor_sync(0xffffffffu, yv[i], off);
            }
            if (lane == 0) {
                float4 o;
                o.x = yv[0] + Dh * xv[0];
                o.y = yv[1] + Dh * xv[1];
                o.z = yv[2] + Dh * xv[2];
                o.w = yv[3] + Dh * xv[3];
                *(float4*)(g_y + (size_t)(blbase + t0 + tt) * D_INNER + h * HEADDIM + p0 + w * 4) = o;
            }
        }
    }
}

// =====================================================================
// mulnorm: y = y * silu(z); y = y * rsqrt(mean(y^2)+1e-5) * norm_w
// one block per (b,l) row; 256 threads * float4 = 1024 elems
// =====================================================================
__global__ __launch_bounds__(256) void mulnorm_kernel(const float* __restrict__ norm_w) {
    __shared__ float red[8];
    __shared__ float rinv;
    const int bl = blockIdx.x, tid = threadIdx.x;
    const int lane = tid & 31, w = tid >> 5;
    float4 yv = *(const float4*)(g_y + (size_t)bl * D_INNER + tid * 4);
    float4 zv = *(const float4*)(g_zx + (size_t)bl * D_IN_PROJ + tid * 4);
    float4 t;
    t.x = yv.x * (zv.x / (1.f + expf(-zv.x)));
    t.y = yv.y * (zv.y / (1.f + expf(-zv.y)));
    t.z = yv.z * (zv.z / (1.f + expf(-zv.z)));
    t.w = yv.w * (zv.w / (1.f + expf(-zv.w)));
    float ss = t.x * t.x + t.y * t.y + t.z * t.z + t.w * t.w;
#pragma unroll
    for (int off = 16; off > 0; off >>= 1) ss += __shfl_xor_sync(0xffffffffu, ss, off);
    if (lane == 0) red[w] = ss;
    __syncthreads();
    if (tid == 0) {
        float tot = 0.f;
#pragma unroll
        for (int i = 0; i < 8; i++) tot += red[i];
        rinv = rsqrtf(tot * (1.f / (float)D_INNER) + 1e-5f);
    }
    __syncthreads();
    const float r = rinv;
    float4 w4 = *(const float4*)(norm_w + tid * 4);
    t.x *= r * w4.x; t.y *= r * w4.y; t.z *= r * w4.z; t.w *= r * w4.w;
    *(float4*)(g_y + (size_t)bl * D_INNER + tid * 4) = t;
}

// =====================================================================
// GEMM2: out[b][d][l] = sum_e Wo[d][e] * y[b*4096+l][e] + x[b][d][l]
// per b: M=512 (d), N=4096 (l), K=1024.  128x128x8 tile.
// =====================================================================
__global__ __launch_bounds__(256) void gemm2_kernel(const float* __restrict__ Wo,
                                                    const float* __restrict__ x,
                                                    float* __restrict__ out) {
    __shared__ float As[8][132];   // [k][d]
    __shared__ float Bs[8][132];   // [k][l]
    const int tid = threadIdx.x;
    const int l0 = blockIdx.x * 128;
    const int d0 = blockIdx.y * 128;
    const int b  = blockIdx.z;
    const float* yp = g_y + (size_t)(b * LSEQ + l0) * D_INNER;

    const int tx = tid & 15, ty = tid >> 4;
    const int ra = tid >> 1;            // 0..127
    const int ka = (tid & 1) * 4;       // 0 or 4

    float acc[8][8];
#pragma unroll
    for (int i = 0; i < 8; i++)
#pragma unroll
        for (int j = 0; j < 8; j++) acc[i][j] = 0.f;

    for (int k0 = 0; k0 < D_INNER; k0 += 8) {
        float4 av = *(const float4*)(Wo + (size_t)(d0 + ra) * D_INNER + k0 + ka);
        float4 bv = *(const float4*)(yp + (size_t)ra * D_INNER + k0 + ka);
        As[ka + 0][ra] = av.x; As[ka + 1][ra] = av.y;
        As[ka + 2][ra] = av.z; As[ka + 3][ra] = av.w;
        Bs[ka + 0][ra] = bv.x; Bs[ka + 1][ra] = bv.y;
        Bs[ka + 2][ra] = bv.z; Bs[ka + 3][ra] = bv.w;
        __syncthreads();
#pragma unroll
        for (int kk = 0; kk < 8; kk++) {
            float a[8], bb[8];
            *(float4*)&a[0]  = *(float4*)&As[kk][ty * 8];
            *(float4*)&a[4]  = *(float4*)&As[kk][ty * 8 + 4];
            *(float4*)&bb[0] = *(float4*)&Bs[kk][tx * 8];
            *(float4*)&bb[4] = *(float4*)&Bs[kk][tx * 8 + 4];
#pragma unroll
            for (int i = 0; i < 8; i++)
#pragma unroll
                for (int j = 0; j < 8; j++)
                    acc[i][j] = fmaf(a[i], bb[j], acc[i][j]);
        }
        __syncthreads();
    }

    const size_t base = (size_t)b * DIM * LSEQ;
#pragma unroll
    for (int i = 0; i < 8; i++) {
        const int d = d0 + ty * 8 + i;
        const size_t off = base + (size_t)d * LSEQ + l0 + tx * 8;
        float4 x0 = *(const float4*)(x + off);
        float4 x1 = *(const float4*)(x + off + 4);
        float4 o0 = make_float4(acc[i][0] + x0.x, acc[i][1] + x0.y,
                                acc[i][2] + x0.z, acc[i][3] + x0.w);
        float4 o1 = make_float4(acc[i][4] + x1.x, acc[i][5] + x1.y,
                                acc[i][6] + x1.z, acc[i][7] + x1.w);
        *(float4*)(out + off)     = o0;
        *(float4*)(out + off + 4) = o1;
    }
}

// =====================================================================
extern "C" void kernel_launch(void* const* d_in, const int* in_sizes, int n_in,
                              void* d_out, int out_size) {
    const float* x          = (const float*)d_in[0];
    const float* in_proj_w  = (const float*)d_in[1];
    const float* conv_w     = (const float*)d_in[2];
    const float* conv_b     = (const float*)d_in[3];
    const float* dt_bias    = (const float*)d_in[4];
    const float* A_log      = (const float*)d_in[5];
    const float* D_param    = (const float*)d_in[6];
    const float* norm_w     = (const float*)d_in[7];
    const float* out_proj_w = (const float*)d_in[8];
    float* out = (float*)d_out;

    // 1. in_proj GEMM: (16384 x 512) @ (512 x 2312)
    gemm1_kernel<<<dim3((D_IN_PROJ + 127) / 128, NBL / 128), 256>>>(x, in_proj_w);
    // 2. dt softplus + dA (reads dt columns of g_zx)
    prep_kernel<<<(NBL * NHEADS) / 256, 256>>>(dt_bias, A_log);
    // 3. depthwise causal conv + SiLU
    conv_kernel<<<((size_t)NBL * CONV_DIM) / 256, 256>>>(conv_w, conv_b);
    // 4. selective scan (+ D skip)
    scan_kernel<<<BSZ * NHEADS * (HEADDIM / 32), 256>>>(D_param);
    // 5. gate + RMSNorm
    mulnorm_kernel<<<NBL, 256>>>(norm_w);
    // 6. out_proj GEMM + residual, transposed store
    gemm2_kernel<<<dim3(LSEQ / 128, DIM / 128, BSZ), 256>>>(out_proj_w, x, out);
}